// round 6
// baseline (speedup 1.0000x reference)
#include <cuda_runtime.h>
#include <cuda_fp16.h>

#define BATCH   8
#define CH      2049          // N/2+1 spectrum bins
#define CHP     2064          // padded row: 2064*8 B, 128B-aligned rows
#define TFR     345           // frames
#define NFFT    4096
#define MH      2048          // NFFT/2 = complex FFT size
#define HOP     1024
#define NFRAMES (BATCH*TFR)   // 2760

// ---------------- scratch (device globals; no allocations) ----------------
__device__ float2 g_spec[NFRAMES * CHP];    // [frame][k] = (Re, Im), padded rows
__device__ __half g_frames[NFRAMES * NFFT]; // [frame][n] windowed time samples (fp16)
__device__ float2 g_twN[MH];                // e^{+2*pi*i*k/4096}
__device__ float2 g_win[MH];                // (hann[2m], hann[2m+1])

// smem bank swizzle (float2 index granularity; 16 float2 = 128B row)
#define SW(p) ((p) ^ (((p) >> 4) & 15))

__device__ __forceinline__ float2 cmul(float2 a, float2 b) {
    return make_float2(a.x*b.x - a.y*b.y, a.x*b.y + a.y*b.x);
}
__device__ __forceinline__ float2 cadd(float2 a, float2 b){ return make_float2(a.x+b.x, a.y+b.y); }
__device__ __forceinline__ float2 csub(float2 a, float2 b){ return make_float2(a.x-b.x, a.y-b.y); }
__device__ __forceinline__ float2 cmuli(float2 a){ return make_float2(-a.y, a.x); }   // i*a

// ---------------- transpose [B, CH, T] -> g_spec, fused fp32 table init -----
__global__ void __launch_bounds__(256) transpose_kernel(const float* __restrict__ re,
                                                        const float* __restrict__ im)
{
    __shared__ float sr[32][65];
    __shared__ float si[32][65];
    int b  = blockIdx.z;
    int k0 = blockIdx.x << 5, t0 = blockIdx.y << 6;
    int tx = threadIdx.x, ty = threadIdx.y;   // ty in [0,8)

    // fused table init: first 8 (x,0,0) blocks cover 2048 ids, fp32 sinpi/cospi
    if (blockIdx.y == 0 && blockIdx.z == 0 && blockIdx.x < 8) {
        int gid = (blockIdx.x << 8) + (ty << 5) + tx;   // 0..2047
        float a = (float)gid * (1.0f / 2048.0f);        // angle in units of pi
        float s, c;
        sincospif(a, &s, &c);
        g_twN[gid] = make_float2(c, s);                 // e^{+i*2pi*gid/4096}
        float c0 = cospif((float)(2*gid)     * (1.0f / 2048.0f));
        float c1 = cospif((float)(2*gid + 1) * (1.0f / 2048.0f));
        g_win[gid] = make_float2(0.5f - 0.5f*c0, 0.5f - 0.5f*c1);
    }

    const float* rb = re + (size_t)b * CH * TFR;
    const float* ib = im + (size_t)b * CH * TFR;
    #pragma unroll
    for (int u = 0; u < 2; u++) {
        int t = t0 + tx + (u << 5);
        bool tok = (t < TFR);
        #pragma unroll
        for (int j = 0; j < 4; j++) {
            int kl = ty + (j << 3);
            int k  = k0 + kl;
            if (k < CH && tok) {
                sr[kl][tx + (u << 5)] = rb[k * TFR + t];
                si[kl][tx + (u << 5)] = ib[k * TFR + t];
            }
        }
    }
    __syncthreads();
    int ko = k0 + tx;
    bool kok = (ko < CH);
    #pragma unroll
    for (int u = 0; u < 2; u++) {
        #pragma unroll
        for (int j = 0; j < 4; j++) {
            int tl = ty + (j << 3) + (u << 5);
            int to = t0 + tl;
            if (kok && to < TFR)
                g_spec[((size_t)b * TFR + to) * CHP + ko] =
                    make_float2(sr[tx][tl], si[tx][tl]);
        }
    }
}

// ---------------- in-place radix-8 Stockham DIF pass (inverse, e^{+}) -------
// Twiddles via direct table lookup: stw[e] = W_2048^e, e < 2048. All exponents
// q*jm (q<=7, jm<=255) stay below 2048 for every pass, so no modulo needed.
__device__ __forceinline__ void radix8_pass_ip(float2* __restrict__ buf,
                                               const float2* __restrict__ stw,
                                               int tid, int m)
{
    int i  = tid & (m - 1);
    int jm = tid - i;

    float2 x0 = buf[SW(tid        )];
    float2 x1 = buf[SW(tid +  256)];
    float2 x2 = buf[SW(tid +  512)];
    float2 x3 = buf[SW(tid +  768)];
    float2 x4 = buf[SW(tid + 1024)];
    float2 x5 = buf[SW(tid + 1280)];
    float2 x6 = buf[SW(tid + 1536)];
    float2 x7 = buf[SW(tid + 1792)];
    float2 w1 = stw[jm];
    float2 w2 = stw[2*jm];
    float2 w3 = stw[3*jm];
    float2 w4 = stw[4*jm];
    float2 w5 = stw[5*jm];
    float2 w6 = stw[6*jm];
    float2 w7 = stw[7*jm];
    __syncthreads();

    float2 ta = cadd(x0, x4), tb = csub(x0, x4);
    float2 tc = cadd(x2, x6), td = cmuli(csub(x2, x6));
    float2 E0 = cadd(ta, tc), E1 = cadd(tb, td);
    float2 E2 = csub(ta, tc), E3 = csub(tb, td);
    float2 sa = cadd(x1, x5), sb = csub(x1, x5);
    float2 sc = cadd(x3, x7), sd = cmuli(csub(x3, x7));
    float2 O0 = cadd(sa, sc), O1 = cadd(sb, sd);
    float2 O2 = csub(sa, sc), O3 = csub(sb, sd);
    const float R = 0.70710678118654752440f;
    O1 = make_float2(R*(O1.x - O1.y), R*(O1.x + O1.y));
    O2 = cmuli(O2);
    O3 = make_float2(R*(-O3.x - O3.y), R*(O3.x - O3.y));

    float2 y0 = cadd(E0, O0), y4 = csub(E0, O0);
    float2 y1 = cadd(E1, O1), y5 = csub(E1, O1);
    float2 y2 = cadd(E2, O2), y6 = csub(E2, O2);
    float2 y3 = cadd(E3, O3), y7 = csub(E3, O3);

    int base = tid + 7 * jm;          // = 8*jm + i
    buf[SW(base      )] = y0;
    buf[SW(base +   m)] = cmul(y1, w1);
    buf[SW(base + 2*m)] = cmul(y2, w2);
    buf[SW(base + 3*m)] = cmul(y3, w3);
    buf[SW(base + 4*m)] = cmul(y4, w4);
    buf[SW(base + 5*m)] = cmul(y5, w5);
    buf[SW(base + 6*m)] = cmul(y6, w6);
    buf[SW(base + 7*m)] = cmul(y7, w7);
    __syncthreads();
}

// ---------------- per-frame inverse real FFT (size 4096) ---------------------
__global__ void __launch_bounds__(256) ifft_kernel()
{
    __shared__ float2 buf[MH];     // single in-place buffer (16 KB)
    __shared__ float2 stw[MH];     // W_2048^e, e in [0,2048) (16 KB)

    int f   = blockIdx.x;
    int tid = threadIdx.x;
    const float2* __restrict__ X = g_spec + (size_t)f * CHP;

#if __CUDA_ARCH__ >= 900
    cudaGridDependencySynchronize();   // wait for transpose (PDL)
#endif

    // build full twiddle table: W_2048^e = W_4096^{2e}; half-circle negation
    #pragma unroll
    for (int j = 0; j < 8; j++) {
        int e = tid + (j << 8);
        if (j < 4) {
            stw[e] = g_twN[2 * e];
        } else {
            float2 w = g_twN[2 * e - 2048];
            stw[e] = make_float2(-w.x, -w.y);
        }
    }

    const float sc = 1.0f / 256.0f;
    #pragma unroll
    for (int j = 0; j < 8; j++) {
        int k = tid + (j << 8);
        float2 Xk = X[k];
        float2 Xc = X[MH - k];
        if (k == 0) { Xk.y = 0.f; Xc.y = 0.f; }
        float ex = sc * (Xk.x + Xc.x);
        float ey = sc * (Xk.y - Xc.y);
        float dx = sc * (Xk.x - Xc.x);
        float dy = sc * (Xk.y + Xc.y);
        float2 w = g_twN[k];
        float ox = dx * w.x - dy * w.y;
        float oy = dx * w.y + dy * w.x;
        buf[SW(k)] = make_float2(ex - oy, ey + ox);
    }
    __syncthreads();

    radix8_pass_ip(buf, stw, tid, 1);
    radix8_pass_ip(buf, stw, tid, 8);
    radix8_pass_ip(buf, stw, tid, 64);

    // final radix-4 pass (m=512, jm=0 -> twiddle-free) fused with window + fp16 store
    __half2* __restrict__ fr = (__half2*)(g_frames + (size_t)f * NFFT);
    #pragma unroll
    for (int j = 0; j < 2; j++) {
        int p = tid + (j << 8);                     // butterfly index in [0,512)
        float2 x0 = buf[SW(p       )];
        float2 x1 = buf[SW(p +  512)];
        float2 x2 = buf[SW(p + 1024)];
        float2 x3 = buf[SW(p + 1536)];
        float2 e  = cadd(x0, x2), o  = cadd(x1, x3);
        float2 em = csub(x0, x2), om = cmuli(csub(x1, x3));
        float2 y0 = cadd(e, o);
        float2 y1 = cadd(em, om);
        float2 y2 = csub(e, o);
        float2 y3 = csub(em, om);
        float2 w;
        w = g_win[p       ]; fr[p       ] = __floats2half2_rn(y0.x*w.x, y0.y*w.y);
        w = g_win[p +  512]; fr[p +  512] = __floats2half2_rn(y1.x*w.x, y1.y*w.y);
        w = g_win[p + 1024]; fr[p + 1024] = __floats2half2_rn(y2.x*w.x, y2.y*w.y);
        w = g_win[p + 1536]; fr[p + 1536] = __floats2half2_rn(y3.x*w.x, y3.y*w.y);
    }
}

// ---------------- gather overlap-add, 16 samples/thread (high MLP) -----------
__global__ void __launch_bounds__(64) ola_kernel(const float* __restrict__ wsi,
                                                 float* __restrict__ out, int outlen)
{
    int s = blockIdx.x;                // 1024-sample output segment
    int b = blockIdx.y;
    int r = threadIdx.x << 4;          // 0..1008, 16 samples per thread
    int j = (s << 10) + r;
    if (j + 16 > outlen) return;       // outlen divisible by 16 -> exact cover
    int p   = j + MH;                  // position in padded signal (skip N/2)
    int seg = p >> 10;                 // = s + 2

    // wsi is an input (independent of ifft) -> prefetch before the PDL sync
    float4 w0 = *(const float4*)(wsi + p);
    float4 w1 = *(const float4*)(wsi + p + 4);
    float4 w2 = *(const float4*)(wsi + p + 8);
    float4 w3 = *(const float4*)(wsi + p + 12);

#if __CUDA_ARCH__ >= 900
    cudaGridDependencySynchronize();   // wait for ifft (PDL)
#endif

    const __half* frbase = g_frames + (size_t)b * TFR * NFFT;
    float acc[16];
    #pragma unroll
    for (int q = 0; q < 16; q++) acc[q] = 0.f;

    #pragma unroll
    for (int d = 0; d < 4; d++) {
        int t = seg - d;
        if (t >= 0 && t < TFR) {
            const __half* src = frbase + (size_t)t * NFFT + r + (d << 10);
            uint4 ra = *(const uint4*)(src);
            uint4 rb = *(const uint4*)(src + 8);
            float2 v;
            v = __half22float2(*(__half2*)&ra.x); acc[0]  += v.x; acc[1]  += v.y;
            v = __half22float2(*(__half2*)&ra.y); acc[2]  += v.x; acc[3]  += v.y;
            v = __half22float2(*(__half2*)&ra.z); acc[4]  += v.x; acc[5]  += v.y;
            v = __half22float2(*(__half2*)&ra.w); acc[6]  += v.x; acc[7]  += v.y;
            v = __half22float2(*(__half2*)&rb.x); acc[8]  += v.x; acc[9]  += v.y;
            v = __half22float2(*(__half2*)&rb.y); acc[10] += v.x; acc[11] += v.y;
            v = __half22float2(*(__half2*)&rb.z); acc[12] += v.x; acc[13] += v.y;
            v = __half22float2(*(__half2*)&rb.w); acc[14] += v.x; acc[15] += v.y;
        }
    }
    float* op = out + (size_t)b * outlen + j;
    *(float4*)(op)      = make_float4(acc[0]*w0.x,  acc[1]*w0.y,  acc[2]*w0.z,  acc[3]*w0.w);
    *(float4*)(op + 4)  = make_float4(acc[4]*w1.x,  acc[5]*w1.y,  acc[6]*w1.z,  acc[7]*w1.w);
    *(float4*)(op + 8)  = make_float4(acc[8]*w2.x,  acc[9]*w2.y,  acc[10]*w2.z, acc[11]*w2.w);
    *(float4*)(op + 12) = make_float4(acc[12]*w3.x, acc[13]*w3.y, acc[14]*w3.z, acc[15]*w3.w);
}

// ---------------- launch -----------------------------------------------------
extern "C" void kernel_launch(void* const* d_in, const int* in_sizes, int n_in,
                              void* d_out, int out_size)
{
    const float* re  = (const float*)d_in[0];
    const float* im  = (const float*)d_in[1];
    // d_in[2] = inverse_basis (unused: replaced analytically by the iFFT)
    const float* wsi = (const float*)d_in[3];
    float* out = (float*)d_out;
    int outlen = out_size / BATCH;     // 352800

    dim3 tgrid((CH + 31) / 32, (TFR + 63) / 64, BATCH);
    transpose_kernel<<<tgrid, dim3(32, 8)>>>(re, im);

    // PDL launches: consumer may begin while predecessor drains; kernels gate
    // on cudaGridDependencySynchronize() before touching produced data.
    cudaLaunchAttribute attr[1];
    attr[0].id = cudaLaunchAttributeProgrammaticStreamSerialization;
    attr[0].val.programmaticStreamSerializationAllowed = 1;

    cudaLaunchConfig_t cfg1 = {};
    cfg1.gridDim = dim3(NFRAMES); cfg1.blockDim = dim3(256);
    cfg1.dynamicSmemBytes = 0; cfg1.stream = 0;
    cfg1.attrs = attr; cfg1.numAttrs = 1;
    if (cudaLaunchKernelEx(&cfg1, ifft_kernel) != cudaSuccess)
        ifft_kernel<<<NFRAMES, 256>>>();

    cudaLaunchConfig_t cfg2 = {};
    cfg2.gridDim = dim3((outlen + 1023) / 1024, BATCH); cfg2.blockDim = dim3(64);
    cfg2.dynamicSmemBytes = 0; cfg2.stream = 0;
    cfg2.attrs = attr; cfg2.numAttrs = 1;
    if (cudaLaunchKernelEx(&cfg2, ola_kernel, wsi, out, outlen) != cudaSuccess)
        ola_kernel<<<dim3((outlen + 1023) / 1024, BATCH), 64>>>(wsi, out, outlen);
}